// round 12
// baseline (speedup 1.0000x reference)
#include <cuda_runtime.h>
#include <cuda_bf16.h>

// Problem constants
constexpr int kN  = 50000;   // nodes
constexpr int kE  = 800000;  // edges per metapath
constexpr int kM  = 4;       // metapaths
constexpr int kH  = 4;       // heads
constexpr int kC  = 32;      // channels per head
constexpr int kIN = 256;     // input dim
constexpr int kD  = 128;     // output dim (H*C)
constexpr int kMN = kM * kN;     // 200000
constexpr int kME = kM * kE;     // 3200000
constexpr int PAD = 64;          // bucket capacity (Poisson(16) tail ~1e-20)

constexpr int NGEMM = (kN + 127) / 128;  // 391 gemm blocks
constexpr int NBUK  = 1250;              // bucket-build blocks

// Scratch (__device__ globals; no cudaMalloc allowed)
__device__ float    g_h[kN * kD];        // projected features fp32, 25.6MB
__device__ unsigned g_hpu[kN * 64];      // packed bf16 messages, 12.8MB
__device__ float    g_adst[kMN * kH];    // per-(m,node) dst logit term
__device__ float    g_asrc[kMN * kH];    // per-(m,node) src logit term
__device__ int      g_cnt[kMN];          // per-(m,node) in-degree
__device__ int      g_bsrc[(long)kMN * PAD];  // padded buckets, 51.2MB

// packed f32x2 FMA: d = a2 * b2 + d  (Blackwell dual-fp32 pipe)
__device__ __forceinline__ void fma2(unsigned long long& d,
                                     unsigned long long a2,
                                     unsigned long long b2) {
    asm("fma.rn.f32x2 %0, %1, %2, %0;" : "+l"(d) : "l"(a2), "l"(b2));
}
__device__ __forceinline__ unsigned long long pack2(float v) {
    unsigned long long r;
    asm("mov.b64 %0, {%1, %1};" : "=l"(r) : "f"(v));
    return r;
}

// ---------------------------------------------------------------------------
// K1 (heterogeneous): blocks [0,NGEMM) compute h = relu(feats@W + b) with a
// double-buffered smem pipeline using packed f32x2 FMAs, writing fp32 +
// packed-bf16 copies AND the fused per-(m,node,head) alpha logit terms;
// blocks [NGEMM, ...) build the padded dst-buckets (overlapped).
// ---------------------------------------------------------------------------
__global__ __launch_bounds__(256, 2) void k_fused(
    const float* __restrict__ A, const float* __restrict__ W,
    const float* __restrict__ bias, const int* __restrict__ ei,
    const float* __restrict__ attn)
{
    __shared__ float As[2][16][132];   // [buf][k][m], padded stride
    __shared__ float Bs[2][16][128];   // [buf][k][n]
    __shared__ float at[kM * kH * 2 * kC];   // 1024 floats

    if (blockIdx.x >= NGEMM) {
        // ---- bucket build (incremental metapath/edge decomposition) ----
        int t = (blockIdx.x - NGEMM) * 256 + threadIdx.x;
        const int stride = NBUK * 256;           // 320000 < kE
        int m = t / kE;
        int e = t - m * kE;
        while (m < kM) {
            int src = ei[(m * 2 + 0) * kE + e];
            int dst = ei[(m * 2 + 1) * kE + e];
            int row = m * kN + dst;
            int pos = atomicAdd(&g_cnt[row], 1);
            if (pos < PAD) g_bsrc[(long)row * PAD + pos] = src;
            e += stride;
            if (e >= kE) { e -= kE; m++; }
        }
        return;
    }

    // ---- GEMM ----
    const int tid  = threadIdx.x;
    const int tr   = tid >> 4;
    const int tc   = tid & 15;
    const int row0 = tr * 8;
    const int col0 = tc * 8;
    const int rowBase = blockIdx.x * 128;

#pragma unroll
    for (int i = 0; i < 4; i++)
        at[tid + i * 256] = attn[tid + i * 256];

    // per-thread load coords
    const int la_r  = tid >> 2;          // A row (of 128), two halves
    const int la_c4 = (tid & 3) << 2;    // A col group of 4
    const int lb_k  = tid >> 5;          // B k row (of 16), two halves
    const int lb_n4 = (tid & 31) << 2;   // B col group of 4

    // packed accumulators: acc2[i][j] = cols (2j, 2j+1) of row i
    unsigned long long acc2[8][4];
#pragma unroll
    for (int i = 0; i < 8; i++)
#pragma unroll
        for (int j = 0; j < 4; j++) acc2[i][j] = 0ull;

    // preload k0 = 0 into buffer 0
    {
#pragma unroll
        for (int i = 0; i < 2; i++) {
            int r  = la_r + i * 64;
            float4 v = make_float4(0.f, 0.f, 0.f, 0.f);
            int gr = rowBase + r;
            if (gr < kN) v = *(const float4*)(A + (long)gr * kIN + la_c4);
            As[0][la_c4 + 0][r] = v.x; As[0][la_c4 + 1][r] = v.y;
            As[0][la_c4 + 2][r] = v.z; As[0][la_c4 + 3][r] = v.w;
        }
#pragma unroll
        for (int i = 0; i < 2; i++) {
            int kk = lb_k + i * 8;
            *(float4*)(&Bs[0][kk][lb_n4]) = *(const float4*)(W + kk * kD + lb_n4);
        }
    }
    __syncthreads();

    int cur = 0;
    for (int k0 = 0; k0 < kIN; k0 += 16) {
        const int nxt = cur ^ 1;
        float4 pa[2], pb[2];
        const bool more = (k0 + 16 < kIN);
        if (more) {
#pragma unroll
            for (int i = 0; i < 2; i++) {
                int r  = la_r + i * 64;
                int gr = rowBase + r;
                pa[i] = make_float4(0.f, 0.f, 0.f, 0.f);
                if (gr < kN)
                    pa[i] = *(const float4*)(A + (long)gr * kIN + k0 + 16 + la_c4);
                pb[i] = *(const float4*)(W + (k0 + 16 + lb_k + i * 8) * kD + lb_n4);
            }
        }
#pragma unroll
        for (int kk = 0; kk < 16; kk++) {
            float ra[8];
            unsigned long long rb2[4];
            *(float4*)(ra)     = *(const float4*)(&As[cur][kk][row0]);
            *(float4*)(ra + 4) = *(const float4*)(&As[cur][kk][row0 + 4]);
            float4 b0 = *(const float4*)(&Bs[cur][kk][col0]);
            float4 b1 = *(const float4*)(&Bs[cur][kk][col0 + 4]);
            rb2[0] = ((unsigned long long*)&b0)[0];
            rb2[1] = ((unsigned long long*)&b0)[1];
            rb2[2] = ((unsigned long long*)&b1)[0];
            rb2[3] = ((unsigned long long*)&b1)[1];
#pragma unroll
            for (int i = 0; i < 8; i++) {
                const unsigned long long a2 = pack2(ra[i]);
#pragma unroll
                for (int j = 0; j < 4; j++)
                    fma2(acc2[i][j], a2, rb2[j]);
            }
        }
        if (more) {
#pragma unroll
            for (int i = 0; i < 2; i++) {
                int r = la_r + i * 64;
                As[nxt][la_c4 + 0][r] = pa[i].x; As[nxt][la_c4 + 1][r] = pa[i].y;
                As[nxt][la_c4 + 2][r] = pa[i].z; As[nxt][la_c4 + 3][r] = pa[i].w;
                *(float4*)(&Bs[nxt][lb_k + i * 8][lb_n4]) = pb[i];
            }
        }
        __syncthreads();
        cur = nxt;
    }

    // epilogue: bias + relu; write fp32 + packed bf16; fused alpha dots.
    const int hh   = tc >> 2;          // head this thread's channels belong to
    const int coff = (tc & 3) * 8;     // channel offset within head
#pragma unroll
    for (int i = 0; i < 8; i++) {
        int gr = rowBase + row0 + i;
        const bool valid = (gr < kN);
        float o[8];
#pragma unroll
        for (int j = 0; j < 4; j++) {
            float2 p = *(float2*)&acc2[i][j];
            o[2 * j]     = fmaxf(p.x + bias[col0 + 2 * j], 0.f);
            o[2 * j + 1] = fmaxf(p.y + bias[col0 + 2 * j + 1], 0.f);
        }
        if (valid) {
            *(float4*)(g_h + (long)gr * kD + col0)     = *(float4*)(o);
            *(float4*)(g_h + (long)gr * kD + col0 + 4) = *(float4*)(o + 4);
            unsigned* up = g_hpu + (long)gr * 64;
#pragma unroll
            for (int j = 0; j < 4; j++) {
                __nv_bfloat162 p = __floats2bfloat162_rn(o[2 * j], o[2 * j + 1]);
                int c = col0 + 2 * j;
                int ui = (tc < 8) ? c : (c - 63);  // 2l or 2l+1
                up[ui] = *(unsigned*)&p;
            }
        }
        // alpha: partial dots over this thread's 8 channels, reduce over the
        // 4 threads (shfl_xor 1,2) covering head hh's 32 channels.
#pragma unroll
        for (int m = 0; m < kM; m++) {
            const float* am = at + (m * kH + hh) * (2 * kC);
            float pl = 0.f, pr = 0.f;
#pragma unroll
            for (int j = 0; j < 8; j++) {
                pl = fmaf(o[j], am[coff + j], pl);
                pr = fmaf(o[j], am[kC + coff + j], pr);
            }
            pl += __shfl_xor_sync(0xffffffffu, pl, 1);
            pl += __shfl_xor_sync(0xffffffffu, pl, 2);
            pr += __shfl_xor_sync(0xffffffffu, pr, 1);
            pr += __shfl_xor_sync(0xffffffffu, pr, 2);
            if (valid && (tid & 3) == 0) {
                g_adst[((long)m * kN + gr) * kH + hh] = pl;
                g_asrc[((long)m * kN + gr) * kH + hh] = pr;
            }
        }
    }
}

// ---------------------------------------------------------------------------
// K3: fused aggregation + relation attention. Warp per node.
// [R4/R9-proven text @ ~110us — FROZEN; three restructures regressed 4-6x]
// ---------------------------------------------------------------------------
__global__ __launch_bounds__(256, 5) void k_aggbeta(
    const float* __restrict__ ral, const float* __restrict__ rar,
    const float* __restrict__ rbias, float* __restrict__ outp)
{
    __shared__ int    ssh[8][PAD];            // src per msg
    __shared__ float2 wsh[8][PAD][2];         // (w_h0,w_h1) per msg per half
    __shared__ float4 sera[8][kM][32];        // spilled era/erb per metapath
    const int w    = threadIdx.x >> 5;
    const int lane = threadIdx.x & 31;
    const int q    = lane >> 4;
    const int n    = blockIdx.x * 8 + w;
    if (n >= kN) return;

    const uint2* __restrict__ hp = (const uint2*)g_hpu + lane;

    for (int m = 0; m < kM; m++) {
        const int row = m * kN + n;
        const float4 ad = *(const float4*)(g_adst + (long)row * 4);
        const int cnt = min(g_cnt[row], PAD);
        const int* __restrict__ bl = g_bsrc + (long)row * PAD;

        // Phase A: weights (lane-parallel, <=2 iterations)
        for (int b = lane; b < cnt; b += 32) {
            int s = bl[b];
            float4 as = *(const float4*)(g_asrc + (long)(m * kN + s) * 4);
            float l0 = ad.x + as.x; l0 = l0 > 0.f ? l0 : 0.2f * l0;
            float l1 = ad.y + as.y; l1 = l1 > 0.f ? l1 : 0.2f * l1;
            float l2 = ad.z + as.z; l2 = l2 > 0.f ? l2 : 0.2f * l2;
            float l3 = ad.w + as.w; l3 = l3 > 0.f ? l3 : 0.2f * l3;
            ssh[w][b]    = s;
            wsh[w][b][0] = make_float2(__expf(l0), __expf(l2));
            wsh[w][b][1] = make_float2(__expf(l1), __expf(l3));
        }
        __syncwarp();

        // Phase B: gather with 8-deep staging
        float2 a0 = make_float2(0.f, 0.f), a1 = make_float2(0.f, 0.f);
        float d0 = 0.f, d1 = 0.f;
        int jb = 0;
        for (; jb + 8 <= cnt; jb += 8) {
            uint2 v[8];
#pragma unroll
            for (int k = 0; k < 8; k++) {
                int s = ssh[w][jb + k];
                v[k] = hp[(long)s * 32];
            }
#pragma unroll
            for (int k = 0; k < 8; k++) {
                const float2 t = wsh[w][jb + k][q];
                const float f0 = __int_as_float(v[k].x << 16);
                const float f1 = __int_as_float(v[k].x & 0xffff0000u);
                const float f2 = __int_as_float(v[k].y << 16);
                const float f3 = __int_as_float(v[k].y & 0xffff0000u);
                a0.x = fmaf(t.x, f0, a0.x); a0.y = fmaf(t.x, f1, a0.y);
                a1.x = fmaf(t.y, f2, a1.x); a1.y = fmaf(t.y, f3, a1.y);
                d0 += t.x; d1 += t.y;
            }
        }
        for (; jb < cnt; jb++) {
            int s = ssh[w][jb];
            uint2 v = hp[(long)s * 32];
            const float2 t = wsh[w][jb][q];
            const float f0 = __int_as_float(v.x << 16);
            const float f1 = __int_as_float(v.x & 0xffff0000u);
            const float f2 = __int_as_float(v.y << 16);
            const float f3 = __int_as_float(v.y & 0xffff0000u);
            a0.x = fmaf(t.x, f0, a0.x); a0.y = fmaf(t.x, f1, a0.y);
            a1.x = fmaf(t.y, f2, a1.x); a1.y = fmaf(t.y, f3, a1.y);
            d0 += t.x; d1 += t.y;
        }
        const float i0 = 1.f / (d0 + 1e-16f);
        const float i1 = 1.f / (d1 + 1e-16f);
        sera[w][m][lane] = make_float4(a0.x * i0, a0.y * i0,
                                       a1.x * i1, a1.y * i1);
        __syncwarp();
    }

    // ---- beta phase ----
    const int h0 = q;
    const int h1 = 2 + q;
    const int cc = (2 * lane) & 31;

    const float2 ha  = *(const float2*)(g_h + (long)n * kD + 2 * lane);
    const float2 hbv = *(const float2*)(g_h + (long)n * kD + 64 + 2 * lane);

    float2 era[5], erb[5];
#pragma unroll
    for (int r = 0; r < 4; r++) {
        float4 t = sera[w][r][lane];
        era[r] = make_float2(t.x, t.y);
        erb[r] = make_float2(t.z, t.w);
    }
    era[4] = ha;   // self relation
    erb[4] = hbv;

    float bta[5], btb[5];
    const float2 rla = *(const float2*)(ral + h0 * kC + cc);
    const float2 rlb = *(const float2*)(ral + h1 * kC + cc);
    const float2 bla = make_float2(fmaxf(ha.x * rla.x, 0.f),
                                   fmaxf(ha.y * rla.y, 0.f));
    const float2 blb = make_float2(fmaxf(hbv.x * rlb.x, 0.f),
                                   fmaxf(hbv.y * rlb.y, 0.f));
#pragma unroll
    for (int r = 0; r < 5; r++) {
        const float2 rra = *(const float2*)(rar + ((r * kH + h0) * kC + cc));
        const float2 rrb = *(const float2*)(rar + ((r * kH + h1) * kC + cc));
        float bax = fmaxf(era[r].x * rra.x, 0.f);
        float bay = fmaxf(era[r].y * rra.y, 0.f);
        float bbx = fmaxf(erb[r].x * rrb.x, 0.f);
        float bby = fmaxf(erb[r].y * rrb.y, 0.f);
        float p0 = bla.x * bax + bla.y * bay;
        float p1 = blb.x * bbx + blb.y * bby;
#pragma unroll
        for (int o = 8; o > 0; o >>= 1) {
            p0 += __shfl_xor_sync(0xffffffffu, p0, o);
            p1 += __shfl_xor_sync(0xffffffffu, p1, o);
        }
        bta[r] = p0 + rbias[r];
        btb[r] = p1 + rbias[r];
    }
    // softmax over relations, then combine + relu
    float m0 = bta[0], m1 = btb[0];
#pragma unroll
    for (int r = 1; r < 5; r++) { m0 = fmaxf(m0, bta[r]); m1 = fmaxf(m1, btb[r]); }
    float s0 = 0.f, s1 = 0.f, e0[5], e1[5];
#pragma unroll
    for (int r = 0; r < 5; r++) {
        e0[r] = expf(bta[r] - m0); s0 += e0[r];
        e1[r] = expf(btb[r] - m1); s1 += e1[r];
    }
    const float is0 = 1.f / s0, is1 = 1.f / s1;
    float2 oa = make_float2(0.f, 0.f), ob = make_float2(0.f, 0.f);
#pragma unroll
    for (int r = 0; r < 5; r++) {
        const float w0 = e0[r] * is0, w1 = e1[r] * is1;
        oa.x = fmaf(w0, era[r].x, oa.x); oa.y = fmaf(w0, era[r].y, oa.y);
        ob.x = fmaf(w1, erb[r].x, ob.x); ob.y = fmaf(w1, erb[r].y, ob.y);
    }
    oa.x = fmaxf(oa.x, 0.f); oa.y = fmaxf(oa.y, 0.f);
    ob.x = fmaxf(ob.x, 0.f); ob.y = fmaxf(ob.y, 0.f);
    *(float2*)(outp + (long)n * kD + 2 * lane)      = oa;
    *(float2*)(outp + (long)n * kD + 64 + 2 * lane) = ob;
}

// ---------------------------------------------------------------------------
extern "C" void kernel_launch(void* const* d_in, const int* in_sizes, int n_in,
                              void* d_out, int out_size)
{
    const float* feats = (const float*)d_in[0];
    const int*   ei    = (const int*)d_in[1];
    const float* W     = (const float*)d_in[2];
    const float* b     = (const float*)d_in[3];
    const float* attn  = (const float*)d_in[4];
    const float* ral   = (const float*)d_in[5];
    const float* rar   = (const float*)d_in[6];
    const float* rbias = (const float*)d_in[7];
    float* outp = (float*)d_out;

    // zero degree counters via a memset node (no alloc; graph-capturable)
    void* cnt_addr = nullptr;
    cudaGetSymbolAddress(&cnt_addr, g_cnt);
    cudaMemsetAsync(cnt_addr, 0, (size_t)kMN * sizeof(int));

    k_fused<<<NGEMM + NBUK, 256>>>(feats, W, b, ei, attn);
    k_aggbeta<<<(kN + 7) / 8, 256>>>(ral, rar, rbias, outp);
}

// round 13
// speedup vs baseline: 1.0513x; 1.0513x over previous
#include <cuda_runtime.h>
#include <cuda_bf16.h>

// Problem constants
constexpr int kN  = 50000;   // nodes
constexpr int kE  = 800000;  // edges per metapath
constexpr int kM  = 4;       // metapaths
constexpr int kH  = 4;       // heads
constexpr int kC  = 32;      // channels per head
constexpr int kIN = 256;     // input dim
constexpr int kD  = 128;     // output dim (H*C)
constexpr int kMN = kM * kN;     // 200000
constexpr int kME = kM * kE;     // 3200000
constexpr int PAD = 64;          // bucket capacity (Poisson(16) tail ~1e-20)

constexpr int NGEMM = (kN + 127) / 128;  // 391 gemm blocks
constexpr int NBUK  = 1250;              // bucket-build blocks

// Scratch (__device__ globals; no cudaMalloc allowed)
__device__ float    g_h[kN * kD];        // projected features fp32, 25.6MB
__device__ unsigned g_hpu[kN * 64];      // packed bf16 messages, 12.8MB
__device__ float    g_adst[kMN * kH];    // per-(m,node) dst logit term
__device__ float    g_asrc[kMN * kH];    // per-(m,node) src logit term
__device__ int      g_cnt[kMN];          // per-(m,node) in-degree
__device__ int      g_bsrc[(long)kMN * PAD];  // padded buckets, 51.2MB

// packed f32x2 FMA: d = a2 * b2 + d  (Blackwell dual-fp32 pipe)
__device__ __forceinline__ void fma2(unsigned long long& d,
                                     unsigned long long a2,
                                     unsigned long long b2) {
    asm("fma.rn.f32x2 %0, %1, %2, %0;" : "+l"(d) : "l"(a2), "l"(b2));
}
__device__ __forceinline__ unsigned long long pack2(float v) {
    unsigned long long r;
    asm("mov.b64 %0, {%1, %1};" : "=l"(r) : "f"(v));
    return r;
}

// ---------------------------------------------------------------------------
// K0: zero the degree counters (vectorized)
// ---------------------------------------------------------------------------
__global__ void k_zero()
{
    int i = blockIdx.x * blockDim.x + threadIdx.x;
    int4* p = (int4*)g_cnt;
    const int n4 = kMN / 4;
    if (i < n4) p[i] = make_int4(0, 0, 0, 0);
}

// ---------------------------------------------------------------------------
// K1 (heterogeneous): blocks [0,NGEMM) compute h = relu(feats@W + b) with a
// double-buffered smem pipeline using packed f32x2 FMAs, writing fp32 +
// packed-bf16 copies AND the fused per-(m,node,head) alpha logit terms;
// blocks [NGEMM, ...) build the padded dst-buckets (overlapped).
// ---------------------------------------------------------------------------
__global__ __launch_bounds__(256, 2) void k_fused(
    const float* __restrict__ A, const float* __restrict__ W,
    const float* __restrict__ bias, const int* __restrict__ ei,
    const float* __restrict__ attn)
{
    __shared__ float As[2][16][132];   // [buf][k][m], padded stride
    __shared__ float Bs[2][16][128];   // [buf][k][n]
    __shared__ float at[kM * kH * 2 * kC];   // 1024 floats

    if (blockIdx.x >= NGEMM) {
        // ---- bucket build ----
        int t = (blockIdx.x - NGEMM) * 256 + threadIdx.x;
        const int stride = NBUK * 256;
        for (; t < kME; t += stride) {
            int m   = t / kE;
            int e   = t - m * kE;
            int src = ei[(m * 2 + 0) * kE + e];
            int dst = ei[(m * 2 + 1) * kE + e];
            int row = m * kN + dst;
            int pos = atomicAdd(&g_cnt[row], 1);
            if (pos < PAD) g_bsrc[(long)row * PAD + pos] = src;
        }
        return;
    }

    // ---- GEMM ----
    const int tid  = threadIdx.x;
    const int tr   = tid >> 4;
    const int tc   = tid & 15;
    const int row0 = tr * 8;
    const int col0 = tc * 8;
    const int rowBase = blockIdx.x * 128;

#pragma unroll
    for (int i = 0; i < 4; i++)
        at[tid + i * 256] = attn[tid + i * 256];

    // per-thread load coords
    const int la_r  = tid >> 2;          // A row (of 128), two halves
    const int la_c4 = (tid & 3) << 2;    // A col group of 4
    const int lb_k  = tid >> 5;          // B k row (of 16), two halves
    const int lb_n4 = (tid & 31) << 2;   // B col group of 4

    // packed accumulators: acc2[i][j] = cols (2j, 2j+1) of row i
    unsigned long long acc2[8][4];
#pragma unroll
    for (int i = 0; i < 8; i++)
#pragma unroll
        for (int j = 0; j < 4; j++) acc2[i][j] = 0ull;

    // preload k0 = 0 into buffer 0
    {
#pragma unroll
        for (int i = 0; i < 2; i++) {
            int r  = la_r + i * 64;
            float4 v = make_float4(0.f, 0.f, 0.f, 0.f);
            int gr = rowBase + r;
            if (gr < kN) v = *(const float4*)(A + (long)gr * kIN + la_c4);
            As[0][la_c4 + 0][r] = v.x; As[0][la_c4 + 1][r] = v.y;
            As[0][la_c4 + 2][r] = v.z; As[0][la_c4 + 3][r] = v.w;
        }
#pragma unroll
        for (int i = 0; i < 2; i++) {
            int kk = lb_k + i * 8;
            *(float4*)(&Bs[0][kk][lb_n4]) = *(const float4*)(W + kk * kD + lb_n4);
        }
    }
    __syncthreads();

    int cur = 0;
    for (int k0 = 0; k0 < kIN; k0 += 16) {
        const int nxt = cur ^ 1;
        float4 pa[2], pb[2];
        const bool more = (k0 + 16 < kIN);
        if (more) {
#pragma unroll
            for (int i = 0; i < 2; i++) {
                int r  = la_r + i * 64;
                int gr = rowBase + r;
                pa[i] = make_float4(0.f, 0.f, 0.f, 0.f);
                if (gr < kN)
                    pa[i] = *(const float4*)(A + (long)gr * kIN + k0 + 16 + la_c4);
                pb[i] = *(const float4*)(W + (k0 + 16 + lb_k + i * 8) * kD + lb_n4);
            }
        }
#pragma unroll
        for (int kk = 0; kk < 16; kk++) {
            float ra[8];
            unsigned long long rb2[4];
            *(float4*)(ra)     = *(const float4*)(&As[cur][kk][row0]);
            *(float4*)(ra + 4) = *(const float4*)(&As[cur][kk][row0 + 4]);
            float4 b0 = *(const float4*)(&Bs[cur][kk][col0]);
            float4 b1 = *(const float4*)(&Bs[cur][kk][col0 + 4]);
            rb2[0] = ((unsigned long long*)&b0)[0];
            rb2[1] = ((unsigned long long*)&b0)[1];
            rb2[2] = ((unsigned long long*)&b1)[0];
            rb2[3] = ((unsigned long long*)&b1)[1];
#pragma unroll
            for (int i = 0; i < 8; i++) {
                const unsigned long long a2 = pack2(ra[i]);
#pragma unroll
                for (int j = 0; j < 4; j++)
                    fma2(acc2[i][j], a2, rb2[j]);
            }
        }
        if (more) {
#pragma unroll
            for (int i = 0; i < 2; i++) {
                int r = la_r + i * 64;
                As[nxt][la_c4 + 0][r] = pa[i].x; As[nxt][la_c4 + 1][r] = pa[i].y;
                As[nxt][la_c4 + 2][r] = pa[i].z; As[nxt][la_c4 + 3][r] = pa[i].w;
                *(float4*)(&Bs[nxt][lb_k + i * 8][lb_n4]) = pb[i];
            }
        }
        __syncthreads();
        cur = nxt;
    }

    // epilogue: bias + relu; write fp32 + packed bf16; fused alpha dots.
    const int hh   = tc >> 2;          // head this thread's channels belong to
    const int coff = (tc & 3) * 8;     // channel offset within head
#pragma unroll
    for (int i = 0; i < 8; i++) {
        int gr = rowBase + row0 + i;
        const bool valid = (gr < kN);
        float o[8];
#pragma unroll
        for (int j = 0; j < 4; j++) {
            float2 p = *(float2*)&acc2[i][j];
            o[2 * j]     = fmaxf(p.x + bias[col0 + 2 * j], 0.f);
            o[2 * j + 1] = fmaxf(p.y + bias[col0 + 2 * j + 1], 0.f);
        }
        if (valid) {
            *(float4*)(g_h + (long)gr * kD + col0)     = *(float4*)(o);
            *(float4*)(g_h + (long)gr * kD + col0 + 4) = *(float4*)(o + 4);
            unsigned* up = g_hpu + (long)gr * 64;
#pragma unroll
            for (int j = 0; j < 4; j++) {
                __nv_bfloat162 p = __floats2bfloat162_rn(o[2 * j], o[2 * j + 1]);
                int c = col0 + 2 * j;
                int ui = (tc < 8) ? c : (c - 63);  // 2l or 2l+1
                up[ui] = *(unsigned*)&p;
            }
        }
        // alpha: partial dots over this thread's 8 channels, reduce over the
        // 4 threads (shfl_xor 1,2) covering head hh's 32 channels.
#pragma unroll
        for (int m = 0; m < kM; m++) {
            const float* am = at + (m * kH + hh) * (2 * kC);
            float pl = 0.f, pr = 0.f;
#pragma unroll
            for (int j = 0; j < 8; j++) {
                pl = fmaf(o[j], am[coff + j], pl);
                pr = fmaf(o[j], am[kC + coff + j], pr);
            }
            pl += __shfl_xor_sync(0xffffffffu, pl, 1);
            pl += __shfl_xor_sync(0xffffffffu, pl, 2);
            pr += __shfl_xor_sync(0xffffffffu, pr, 1);
            pr += __shfl_xor_sync(0xffffffffu, pr, 2);
            if (valid && (tid & 3) == 0) {
                g_adst[((long)m * kN + gr) * kH + hh] = pl;
                g_asrc[((long)m * kN + gr) * kH + hh] = pr;
            }
        }
    }
}

// ---------------------------------------------------------------------------
// K3: fused aggregation + relation attention. Warp per node.
// [R4/R9-proven text @ ~110us — FROZEN; three restructures regressed 4-6x]
// ---------------------------------------------------------------------------
__global__ __launch_bounds__(256, 5) void k_aggbeta(
    const float* __restrict__ ral, const float* __restrict__ rar,
    const float* __restrict__ rbias, float* __restrict__ outp)
{
    __shared__ int    ssh[8][PAD];            // src per msg
    __shared__ float2 wsh[8][PAD][2];         // (w_h0,w_h1) per msg per half
    __shared__ float4 sera[8][kM][32];        // spilled era/erb per metapath
    const int w    = threadIdx.x >> 5;
    const int lane = threadIdx.x & 31;
    const int q    = lane >> 4;
    const int n    = blockIdx.x * 8 + w;
    if (n >= kN) return;

    const uint2* __restrict__ hp = (const uint2*)g_hpu + lane;

    for (int m = 0; m < kM; m++) {
        const int row = m * kN + n;
        const float4 ad = *(const float4*)(g_adst + (long)row * 4);
        const int cnt = min(g_cnt[row], PAD);
        const int* __restrict__ bl = g_bsrc + (long)row * PAD;

        // Phase A: weights (lane-parallel, <=2 iterations)
        for (int b = lane; b < cnt; b += 32) {
            int s = bl[b];
            float4 as = *(const float4*)(g_asrc + (long)(m * kN + s) * 4);
            float l0 = ad.x + as.x; l0 = l0 > 0.f ? l0 : 0.2f * l0;
            float l1 = ad.y + as.y; l1 = l1 > 0.f ? l1 : 0.2f * l1;
            float l2 = ad.z + as.z; l2 = l2 > 0.f ? l2 : 0.2f * l2;
            float l3 = ad.w + as.w; l3 = l3 > 0.f ? l3 : 0.2f * l3;
            ssh[w][b]    = s;
            wsh[w][b][0] = make_float2(__expf(l0), __expf(l2));
            wsh[w][b][1] = make_float2(__expf(l1), __expf(l3));
        }
        __syncwarp();

        // Phase B: gather with 8-deep staging
        float2 a0 = make_float2(0.f, 0.f), a1 = make_float2(0.f, 0.f);
        float d0 = 0.f, d1 = 0.f;
        int jb = 0;
        for (; jb + 8 <= cnt; jb += 8) {
            uint2 v[8];
#pragma unroll
            for (int k = 0; k < 8; k++) {
                int s = ssh[w][jb + k];
                v[k] = hp[(long)s * 32];
            }
#pragma unroll
            for (int k = 0; k < 8; k++) {
                const float2 t = wsh[w][jb + k][q];
                const float f0 = __int_as_float(v[k].x << 16);
                const float f1 = __int_as_float(v[k].x & 0xffff0000u);
                const float f2 = __int_as_float(v[k].y << 16);
                const float f3 = __int_as_float(v[k].y & 0xffff0000u);
                a0.x = fmaf(t.x, f0, a0.x); a0.y = fmaf(t.x, f1, a0.y);
                a1.x = fmaf(t.y, f2, a1.x); a1.y = fmaf(t.y, f3, a1.y);
                d0 += t.x; d1 += t.y;
            }
        }
        for (; jb < cnt; jb++) {
            int s = ssh[w][jb];
            uint2 v = hp[(long)s * 32];
            const float2 t = wsh[w][jb][q];
            const float f0 = __int_as_float(v.x << 16);
            const float f1 = __int_as_float(v.x & 0xffff0000u);
            const float f2 = __int_as_float(v.y << 16);
            const float f3 = __int_as_float(v.y & 0xffff0000u);
            a0.x = fmaf(t.x, f0, a0.x); a0.y = fmaf(t.x, f1, a0.y);
            a1.x = fmaf(t.y, f2, a1.x); a1.y = fmaf(t.y, f3, a1.y);
            d0 += t.x; d1 += t.y;
        }
        const float i0 = 1.f / (d0 + 1e-16f);
        const float i1 = 1.f / (d1 + 1e-16f);
        sera[w][m][lane] = make_float4(a0.x * i0, a0.y * i0,
                                       a1.x * i1, a1.y * i1);
        __syncwarp();
    }

    // ---- beta phase ----
    const int h0 = q;
    const int h1 = 2 + q;
    const int cc = (2 * lane) & 31;

    const float2 ha  = *(const float2*)(g_h + (long)n * kD + 2 * lane);
    const float2 hbv = *(const float2*)(g_h + (long)n * kD + 64 + 2 * lane);

    float2 era[5], erb[5];
#pragma unroll
    for (int r = 0; r < 4; r++) {
        float4 t = sera[w][r][lane];
        era[r] = make_float2(t.x, t.y);
        erb[r] = make_float2(t.z, t.w);
    }
    era[4] = ha;   // self relation
    erb[4] = hbv;

    float bta[5], btb[5];
    const float2 rla = *(const float2*)(ral + h0 * kC + cc);
    const float2 rlb = *(const float2*)(ral + h1 * kC + cc);
    const float2 bla = make_float2(fmaxf(ha.x * rla.x, 0.f),
                                   fmaxf(ha.y * rla.y, 0.f));
    const float2 blb = make_float2(fmaxf(hbv.x * rlb.x, 0.f),
                                   fmaxf(hbv.y * rlb.y, 0.f));
#pragma unroll
    for (int r = 0; r < 5; r++) {
        const float2 rra = *(const float2*)(rar + ((r * kH + h0) * kC + cc));
        const float2 rrb = *(const float2*)(rar + ((r * kH + h1) * kC + cc));
        float bax = fmaxf(era[r].x * rra.x, 0.f);
        float bay = fmaxf(era[r].y * rra.y, 0.f);
        float bbx = fmaxf(erb[r].x * rrb.x, 0.f);
        float bby = fmaxf(erb[r].y * rrb.y, 0.f);
        float p0 = bla.x * bax + bla.y * bay;
        float p1 = blb.x * bbx + blb.y * bby;
#pragma unroll
        for (int o = 8; o > 0; o >>= 1) {
            p0 += __shfl_xor_sync(0xffffffffu, p0, o);
            p1 += __shfl_xor_sync(0xffffffffu, p1, o);
        }
        bta[r] = p0 + rbias[r];
        btb[r] = p1 + rbias[r];
    }
    // softmax over relations, then combine + relu
    float m0 = bta[0], m1 = btb[0];
#pragma unroll
    for (int r = 1; r < 5; r++) { m0 = fmaxf(m0, bta[r]); m1 = fmaxf(m1, btb[r]); }
    float s0 = 0.f, s1 = 0.f, e0[5], e1[5];
#pragma unroll
    for (int r = 0; r < 5; r++) {
        e0[r] = expf(bta[r] - m0); s0 += e0[r];
        e1[r] = expf(btb[r] - m1); s1 += e1[r];
    }
    const float is0 = 1.f / s0, is1 = 1.f / s1;
    float2 oa = make_float2(0.f, 0.f), ob = make_float2(0.f, 0.f);
#pragma unroll
    for (int r = 0; r < 5; r++) {
        const float w0 = e0[r] * is0, w1 = e1[r] * is1;
        oa.x = fmaf(w0, era[r].x, oa.x); oa.y = fmaf(w0, era[r].y, oa.y);
        ob.x = fmaf(w1, erb[r].x, ob.x); ob.y = fmaf(w1, erb[r].y, ob.y);
    }
    oa.x = fmaxf(oa.x, 0.f); oa.y = fmaxf(oa.y, 0.f);
    ob.x = fmaxf(ob.x, 0.f); ob.y = fmaxf(ob.y, 0.f);
    *(float2*)(outp + (long)n * kD + 2 * lane)      = oa;
    *(float2*)(outp + (long)n * kD + 64 + 2 * lane) = ob;
}

// ---------------------------------------------------------------------------
extern "C" void kernel_launch(void* const* d_in, const int* in_sizes, int n_in,
                              void* d_out, int out_size)
{
    const float* feats = (const float*)d_in[0];
    const int*   ei    = (const int*)d_in[1];
    const float* W     = (const float*)d_in[2];
    const float* b     = (const float*)d_in[3];
    const float* attn  = (const float*)d_in[4];
    const float* ral   = (const float*)d_in[5];
    const float* rar   = (const float*)d_in[6];
    const float* rbias = (const float*)d_in[7];
    float* outp = (float*)d_out;

    k_zero<<<(kMN / 4 + 255) / 256, 256>>>();
    k_fused<<<NGEMM + NBUK, 256>>>(feats, W, b, ei, attn);
    k_aggbeta<<<(kN + 7) / 8, 256>>>(ral, rar, rbias, outp);
}